// round 6
// baseline (speedup 1.0000x reference)
#include <cuda_runtime.h>
#include <cstdint>

// Problem constants (B=256, T=2048, D=128)
#define BB 256
#define TT 2048
#define DD 128
#define MM (BB * TT)          // 524288 rows of the projection GEMM

// Scratch: [m][3][128] fp32 : j=0 -> E = X@We^T + be
//                             j=1 -> L = sigmoid(X@Wl^T + bl)
//                             j=2 -> W = sigmoid(X@Ww^T + bw)
__device__ float g_elw[(size_t)MM * 384];

// ---------------------------------------------------------------------------
// helpers
// ---------------------------------------------------------------------------
__device__ __forceinline__ uint32_t f2tf(float f) {
    uint32_t r;
    asm("cvt.rna.tf32.f32 %0, %1;" : "=r"(r) : "f"(f));
    return r;
}

__device__ __forceinline__ unsigned long long ffma2(unsigned long long a,
                                                    unsigned long long b,
                                                    unsigned long long c) {
    unsigned long long d;
    asm("fma.rn.f32x2 %0, %1, %2, %3;" : "=l"(d) : "l"(a), "l"(b), "l"(c));
    return d;
}

__device__ __forceinline__ float2 u2f2(unsigned long long v) {
    float2 r;
    asm("mov.b64 {%0,%1}, %2;" : "=f"(r.x), "=f"(r.y) : "l"(v));
    return r;
}

__device__ __forceinline__ void cp_async16(uint32_t dst_smem, const void* src) {
    asm volatile("cp.async.cg.shared.global [%0], [%1], 16;\n"
                 :: "r"(dst_smem), "l"(src));
}

// ---------------------------------------------------------------------------
// Kernel 1: fused 3-way projection GEMM (tf32 mma.sync), epilogue bias+sigmoid
//   C[m,n] = sum_k X[m,k] * Wj[n,k]   (Wj row-major == col-major B operand)
// CTA: 256 threads (8 warps), M_TILE=128, N=128 per weight, K=128 in 2 halves.
// smem: Xs[128][132] tf32 (67.6KB) + Ws[128][68] tf32 (34.8KB) = 102.4KB dyn.
// ---------------------------------------------------------------------------
__global__ __launch_bounds__(256) void proj_kernel(
    const float* __restrict__ X,
    const float* __restrict__ We, const float* __restrict__ be,
    const float* __restrict__ Wl, const float* __restrict__ bl,
    const float* __restrict__ Ww, const float* __restrict__ bw)
{
    extern __shared__ uint32_t smem[];
    uint32_t* Xs = smem;                 // [128][132]
    uint32_t* Ws = smem + 128 * 132;     // [128][68]

    const int tid  = threadIdx.x;
    const int warp = tid >> 5;
    const int lane = tid & 31;
    const int g    = lane >> 2;          // 0..7
    const int c    = lane & 3;           // 0..3
    const long m0  = (long)blockIdx.x * 128;

    // ---- load X tile (coalesced float4), convert to tf32 into smem ----
    const float4* X4 = (const float4*)(X + m0 * DD);
    #pragma unroll
    for (int i = 0; i < 16; i++) {
        int idx = tid + i * 256;         // 0..4095 float4s
        int row = idx >> 5;              // 32 float4 per row
        int c4  = idx & 31;
        float4 v = X4[row * 32 + c4];
        uint4 u = make_uint4(f2tf(v.x), f2tf(v.y), f2tf(v.z), f2tf(v.w));
        *(uint4*)&Xs[row * 132 + c4 * 4] = u;
    }
    __syncthreads();

    // ---- A fragments for the full K=128, reused for all 3 weights ----
    uint32_t a[16][4];
    {
        int r0 = warp * 16 + g;
        #pragma unroll
        for (int kt = 0; kt < 16; kt++) {
            int k0 = kt * 8 + c;
            a[kt][0] = Xs[r0 * 132 + k0];
            a[kt][1] = Xs[(r0 + 8) * 132 + k0];
            a[kt][2] = Xs[r0 * 132 + k0 + 4];
            a[kt][3] = Xs[(r0 + 8) * 132 + k0 + 4];
        }
    }

    #pragma unroll 1
    for (int j = 0; j < 3; j++) {
        const float* Wj = (j == 0) ? We : ((j == 1) ? Wl : Ww);
        const float* bj = (j == 0) ? be : ((j == 1) ? bl : bw);

        float acc[16][4];
        #pragma unroll
        for (int nt = 0; nt < 16; nt++)
            #pragma unroll
            for (int q = 0; q < 4; q++) acc[nt][q] = 0.0f;

        #pragma unroll 1
        for (int kc = 0; kc < 2; kc++) {
            __syncthreads();   // previous Ws consumers done
            // stage W[:, kc*64 : kc*64+64] as tf32
            #pragma unroll
            for (int i = 0; i < 8; i++) {
                int idx = tid + i * 256;   // 0..2047 float4s
                int row = idx >> 4;        // 16 float4 per row-chunk
                int c4  = idx & 15;
                float4 v = *(const float4*)&Wj[row * 128 + kc * 64 + c4 * 4];
                uint4 u = make_uint4(f2tf(v.x), f2tf(v.y), f2tf(v.z), f2tf(v.w));
                *(uint4*)&Ws[row * 68 + c4 * 4] = u;
            }
            __syncthreads();

            #pragma unroll
            for (int kt = 0; kt < 8; kt++) {
                int ktg = kc * 8 + kt;
                #pragma unroll
                for (int nt = 0; nt < 16; nt++) {
                    int n  = nt * 8 + g;
                    int kk = kt * 8 + c;
                    uint32_t b0 = Ws[n * 68 + kk];
                    uint32_t b1 = Ws[n * 68 + kk + 4];
                    asm volatile(
                        "mma.sync.aligned.m16n8k8.row.col.f32.tf32.tf32.f32 "
                        "{%0,%1,%2,%3}, {%4,%5,%6,%7}, {%8,%9}, {%0,%1,%2,%3};\n"
                        : "+f"(acc[nt][0]), "+f"(acc[nt][1]),
                          "+f"(acc[nt][2]), "+f"(acc[nt][3])
                        : "r"(a[ktg][0]), "r"(a[ktg][1]),
                          "r"(a[ktg][2]), "r"(a[ktg][3]),
                          "r"(b0), "r"(b1));
                }
            }
        }

        // ---- epilogue: bias (+ sigmoid for j>0), store interleaved ----
        long row0 = m0 + warp * 16 + g;
        #pragma unroll
        for (int nt = 0; nt < 16; nt++) {
            int col = nt * 8 + 2 * c;
            float2 bb = *(const float2*)&bj[col];
            float v0 = acc[nt][0] + bb.x;
            float v1 = acc[nt][1] + bb.y;
            float v2 = acc[nt][2] + bb.x;
            float v3 = acc[nt][3] + bb.y;
            if (j > 0) {
                v0 = 1.0f / (1.0f + __expf(-v0));
                v1 = 1.0f / (1.0f + __expf(-v1));
                v2 = 1.0f / (1.0f + __expf(-v2));
                v3 = 1.0f / (1.0f + __expf(-v3));
            }
            *(float2*)&g_elw[(row0 * 3 + j) * 128 + col]       = make_float2(v0, v1);
            *(float2*)&g_elw[((row0 + 8) * 3 + j) * 128 + col] = make_float2(v2, v3);
        }
    }
}

// ---------------------------------------------------------------------------
// Kernel 2: persistent recurrence. 128 CTAs x 256 threads; CTA owns 2 batch
// rows; thread (r,e) owns lane e of row r, holds Wp row e in 64 f32x2 regs.
// e/l/w streamed via depth-4 cp.async ring; belief broadcast through smem.
// ---------------------------------------------------------------------------
__global__ __launch_bounds__(256, 1) void recur_kernel(
    const float* __restrict__ Wp, const float* __restrict__ bp,
    float* __restrict__ out)
{
    __shared__ __align__(16) float bel[2][128];
    __shared__ __align__(16) float ring[4][2][384];   // [slot][row][E|L|W]

    const int tid = threadIdx.x;
    const int r   = tid >> 7;       // 0..1 local batch row
    const int e   = tid & 127;      // output lane
    const long b  = (long)blockIdx.x * 2 + r;

    // Wp row e as packed f32x2
    unsigned long long wp[64];
    const unsigned long long* wrow = (const unsigned long long*)(Wp + e * 128);
    #pragma unroll
    for (int i = 0; i < 64; i++) wp[i] = wrow[i];
    const float bias = bp[e];

    bel[r][e] = 0.0f;
    float belr = 0.0f;

    // prefetch lane assignment (first 192 threads move 2 rows x 1536B per step)
    const int  cp_row = (tid < 96) ? 0 : 1;
    const int  cp_k   = (tid % 96) * 4;
    const bool cp_on  = (tid < 192);
    const float* src_base =
        g_elw + ((long)(blockIdx.x * 2 + cp_row) * TT) * 384 + cp_k;
    const uint32_t ring_base =
        (uint32_t)__cvta_generic_to_shared(&ring[0][0][0]);
    const uint32_t dst_off = (uint32_t)((cp_row * 384 + cp_k) * 4);

    // prologue: fill slots 0..3 (t = 0..3)
    for (int s = 0; s < 4; s++) {
        if (cp_on) cp_async16(ring_base + (uint32_t)s * 3072u + dst_off,
                              src_base + (long)s * 384);
        asm volatile("cp.async.commit_group;\n");
    }
    __syncthreads();

    float* outp = out + b * (long)TT * 128 + e;

    for (int t = 0; t < TT; t++) {
        const int slot = t & 3;
        asm volatile("cp.async.wait_group 3;\n");
        __syncthreads();   // ring[slot] visible everywhere; bel(t-1) visible

        float ev = ring[slot][r][e];
        float lv = ring[slot][r][128 + e];
        float wv = ring[slot][r][256 + e];

        const ulonglong2* bl2 = (const ulonglong2*)&bel[r][0];
        unsigned long long acc0 = 0ull, acc1 = 0ull;
        #pragma unroll
        for (int i = 0; i < 32; i++) {
            ulonglong2 bv = bl2[i];
            acc0 = ffma2(wp[2 * i],     bv.x, acc0);
            acc1 = ffma2(wp[2 * i + 1], bv.y, acc1);
        }
        float2 s0 = u2f2(acc0);
        float2 s1 = u2f2(acc1);
        float pre  = (s0.x + s0.y) + (s1.x + s1.y) + bias + ev;
        float cand = tanhf(pre);
        float nb   = lv * belr + wv * cand;

        outp[(long)t * 128] = nb;
        belr = nb;

        __syncthreads();   // all reads of bel done before overwrite
        bel[r][e] = nb;

        // refill this slot with step t+4
        if (t + 4 < TT && cp_on)
            cp_async16(ring_base + (uint32_t)slot * 3072u + dst_off,
                       src_base + (long)(t + 4) * 384);
        asm volatile("cp.async.commit_group;\n");
    }
}

// ---------------------------------------------------------------------------
// launch
// ---------------------------------------------------------------------------
extern "C" void kernel_launch(void* const* d_in, const int* in_sizes, int n_in,
                              void* d_out, int out_size) {
    const float* X  = (const float*)d_in[0];
    const float* We = (const float*)d_in[1];
    const float* be = (const float*)d_in[2];
    const float* Wp = (const float*)d_in[3];
    const float* bp = (const float*)d_in[4];
    const float* Wl = (const float*)d_in[5];
    const float* bl = (const float*)d_in[6];
    const float* Ww = (const float*)d_in[7];
    const float* bw = (const float*)d_in[8];
    float* out = (float*)d_out;

    // 102.4KB dynamic smem for the projection GEMM (idempotent; the first,
    // non-captured correctness call establishes it).
    cudaFuncSetAttribute(proj_kernel,
                         cudaFuncAttributeMaxDynamicSharedMemorySize, 102400);

    proj_kernel<<<MM / 128, 256, 102400>>>(X, We, be, Wl, bl, Ww, bw);
    recur_kernel<<<BB / 2, 256>>>(Wp, bp, out);
}